// round 11
// baseline (speedup 1.0000x reference)
#include <cuda_runtime.h>
#include <cstdint>

// MoE gating, exact fp32, K-packed f32x2 GEMM, 16 warps/SM (4/SMSP).
// x:[16384,1024] f32, gate_w:[64,1024] f32.
// out (f32): top_scores [T,2] | top_idx [T,2] | total_loss [1].

#define H      1024
#define NE     64
#define TM     64
#define NT     256
#define KC     32
#define NSTEP  16                  // 512 k per half / KC
#define RS     36                  // smem row stride (floats)
#define XLo    0
#define XHi    (64 * RS)           // 2304
#define WLo    (128 * RS)          // 4608
#define WHi    (192 * RS)          // 6912
#define STG    (256 * RS)          // 9216 floats / stage
#define DSMEM  (2 * STG * 4)       // 73728 B
#define SPS    65
#define NBLK   256

__device__ float    g_pexp[NBLK * NE];
__device__ float    g_pz2[NBLK];
__device__ unsigned g_cnt = 0;

typedef unsigned long long ull;

__device__ __forceinline__ void fma2(ull& d, ull a, ull b) {
    asm("fma.rn.f32x2 %0, %1, %2, %0;" : "+l"(d) : "l"(a), "l"(b));
}
__device__ __forceinline__ uint32_t su32(const void* p) {
    uint32_t a;
    asm("{ .reg .u64 t; cvta.to.shared.u64 t, %1; cvt.u32.u64 %0, t; }"
        : "=r"(a) : "l"(p));
    return a;
}
__device__ __forceinline__ void cpa16(uint32_t dst, const float* src) {
    asm volatile("cp.async.cg.shared.global [%0], [%1], 16;" :: "r"(dst), "l"(src));
}

__global__ void __launch_bounds__(NT, 2) moe_gate(const float* __restrict__ x,
                                                  const float* __restrict__ w,
                                                  float* __restrict__ out,
                                                  int T) {
    extern __shared__ __align__(16) float dsm[];
    __shared__ float    s_red[8];
    __shared__ float    s_lz[16];
    __shared__ unsigned s_last;

    const int tid  = threadIdx.x;
    const int wid  = tid >> 5;
    const int lid  = tid & 31;
    const int tBlk = blockIdx.x * TM;
    const uint32_t sb = su32(dsm);

    // warp roles: tokhalf x ehalf x khalf
    const int tokhalf = wid >> 2;
    const int ehalf   = (wid >> 1) & 1;
    const int khalf   = wid & 1;
    // lane tile: 4 tokens {ty+8i}, 8 experts {tx+4j}
    const int tx = lid & 3;
    const int ty = lid >> 2;

    ull acc[4][8];
#pragma unroll
    for (int i = 0; i < 4; i++)
#pragma unroll
        for (int j = 0; j < 8; j++) acc[i][j] = 0ull;

    const int sq = tid & 7;                // 16B quad within 32-float row

#define STAGE(s_, slot_) do {                                                    \
    int _k0 = (s_) * KC;                                                         \
    uint32_t _sbase = sb + (slot_) * (STG * 4);                                  \
    _Pragma("unroll")                                                            \
    for (int r = 0; r < 2; r++) {                                                \
        int t_ = (r * NT + tid) >> 3;                                            \
        const float* srcL = x + (size_t)(tBlk + t_) * H + _k0 + sq * 4;          \
        cpa16(_sbase + (XLo + t_ * RS + sq * 4) * 4, srcL);                      \
        cpa16(_sbase + (XHi + t_ * RS + sq * 4) * 4, srcL + 512);                \
    }                                                                            \
    _Pragma("unroll")                                                            \
    for (int r = 0; r < 2; r++) {                                                \
        int e_ = (r * NT + tid) >> 3;                                            \
        const float* srcW = w + (size_t)e_ * H + _k0 + sq * 4;                   \
        cpa16(_sbase + (WLo + e_ * RS + sq * 4) * 4, srcW);                      \
        cpa16(_sbase + (WHi + e_ * RS + sq * 4) * 4, srcW + 512);                \
    }                                                                            \
} while (0)

    // prologue
    STAGE(0, 0);
    asm volatile("cp.async.commit_group;" ::: "memory");

#pragma unroll 1
    for (int s = 0; s < NSTEP; s++) {
        asm volatile("cp.async.wait_group 0;" ::: "memory");
        __syncthreads();
        if (s + 1 < NSTEP) STAGE(s + 1, (s + 1) & 1);
        asm volatile("cp.async.commit_group;" ::: "memory");

        const float* xs = dsm + (s & 1) * STG + (khalf ? XHi : XLo)
                          + (tokhalf * 32 + ty) * RS;
        const float* ws = dsm + (s & 1) * STG + (khalf ? WHi : WLo)
                          + (ehalf * 32 + tx) * RS;
#pragma unroll 4
        for (int kh = 0; kh < 16; kh++) {
            ull a[4], b[8];
#pragma unroll
            for (int i = 0; i < 4; i++)
                a[i] = *(const ull*)(xs + i * 8 * RS + 2 * kh);
#pragma unroll
            for (int j = 0; j < 8; j++)
                b[j] = *(const ull*)(ws + j * 4 * RS + 2 * kh);
#pragma unroll
            for (int i = 0; i < 4; i++)
#pragma unroll
                for (int j = 0; j < 8; j++)
                    fma2(acc[i][j], a[i], b[j]);
        }
    }
    __syncthreads();

    // ---- merge k-halves: logits -> sP[64][SPS] ----
    float* sP   = dsm;                 // 64*65 = 4160 floats
    float* sInv = dsm + TM * SPS;      // 64
    if (khalf == 0) {
#pragma unroll
        for (int i = 0; i < 4; i++)
#pragma unroll
            for (int j = 0; j < 8; j++) {
                float2 f = *(float2*)&acc[i][j];
                sP[(tokhalf * 32 + ty + 8 * i) * SPS + ehalf * 32 + tx + 4 * j] = f.x + f.y;
            }
    }
    __syncthreads();
    if (khalf == 1) {
#pragma unroll
        for (int i = 0; i < 4; i++)
#pragma unroll
            for (int j = 0; j < 8; j++) {
                float2 f = *(float2*)&acc[i][j];
                sP[(tokhalf * 32 + ty + 8 * i) * SPS + ehalf * 32 + tx + 4 * j] += f.x + f.y;
            }
    }
    __syncthreads();

    // ---- per-token softmax / top-2 ----
    float zsq = 0.0f;
    if (tid < TM) {
        float* row = sP + tid * SPS;
        float b1 = -1e30f, b2 = -1e30f;
        int   i1 = 0, i2 = 0;
#pragma unroll 8
        for (int e = 0; e < NE; e++) {
            float l = row[e];
            if (l > b1)      { b2 = b1; i2 = i1; b1 = l; i1 = e; }
            else if (l > b2) { b2 = l;  i2 = e; }
        }
        float m = b1, sum = 0.0f;
#pragma unroll 8
        for (int e = 0; e < NE; e++) {
            float ex = __expf(row[e] - m);
            sum += ex;
            row[e] = ex;
        }
        float inv = 1.0f / sum;
        sInv[tid] = inv;
        float z = m + __logf(sum);
        zsq = z * z;
        float p1 = __expf(b1 - m) * inv;
        float p2 = __expf(b2 - m) * inv;
        float dd = __expf(p2 - p1);
        int gt = tBlk + tid;
        out[2 * gt]             = 1.0f / (1.0f + dd);
        out[2 * gt + 1]         = dd / (1.0f + dd);
        out[2 * T + 2 * gt]     = (float)i1;
        out[2 * T + 2 * gt + 1] = (float)i2;
    }

    // ---- loss partials ----
#pragma unroll
    for (int off = 16; off > 0; off >>= 1)
        zsq += __shfl_down_sync(0xffffffffu, zsq, off);
    if (lid == 0) s_red[wid] = zsq;
    __syncthreads();
    if (tid == 0) {
        float s = 0.0f;
#pragma unroll
        for (int i = 0; i < 8; i++) s += s_red[i];
        g_pz2[blockIdx.x] = s;
    }
    if (tid < NE) {
        float s = 0.0f;
#pragma unroll 4
        for (int t = 0; t < TM; t++) s += sP[t * SPS + tid] * sInv[t];
        g_pexp[blockIdx.x * NE + tid] = s;
    }

    // ---- fused finalize: last block computes the loss ----
    __threadfence();
    __syncthreads();
    if (tid == 0)
        s_last = (atomicAdd(&g_cnt, 1u) == (unsigned)(gridDim.x - 1)) ? 1u : 0u;
    __syncthreads();
    if (s_last) {
        __threadfence();
        int e = tid & 63, part = tid >> 6;           // part 0..3
        float s = 0.0f;
#pragma unroll 4
        for (int b = part; b < NBLK; b += 4) s += g_pexp[b * NE + e];
        float z2 = g_pz2[tid];                        // NBLK == NT == 256
        __syncthreads();
        float* redA = dsm;           // [4][64]
        float* redZ = dsm + 256;     // [256]
        redA[part * 64 + e] = s;
        redZ[tid] = z2;
        __syncthreads();
        if (tid < 64) {
            float load = (redA[tid] + redA[64 + tid] + redA[128 + tid] + redA[192 + tid]) / (float)T;
            float dv = load - 1.0f / 64.0f;
            float lb = dv * dv;
            float zz = redZ[tid] + redZ[tid + 64] + redZ[tid + 128] + redZ[tid + 192];
#pragma unroll
            for (int off = 16; off > 0; off >>= 1) {
                lb += __shfl_down_sync(0xffffffffu, lb, off);
                zz += __shfl_down_sync(0xffffffffu, zz, off);
            }
            if (lid == 0) { s_lz[wid] = lb; s_lz[8 + wid] = zz; }
        }
        __syncthreads();
        if (tid == 0) {
            out[4 * T] = 0.01f * 64.0f * (s_lz[0] + s_lz[1])
                       + 1e-4f * ((s_lz[8] + s_lz[9]) / (float)T);
            g_cnt = 0;
        }
    }
}

extern "C" void kernel_launch(void* const* d_in, const int* in_sizes, int n_in,
                              void* d_out, int out_size) {
    const float* x = (const float*)d_in[0];
    const float* w = (const float*)d_in[1];
    float* out = (float*)d_out;
    int T = in_sizes[0] / H;   // 16384
    cudaFuncSetAttribute(moe_gate, cudaFuncAttributeMaxDynamicSharedMemorySize, DSMEM);
    moe_gate<<<T / TM, NT, DSMEM>>>(x, w, out, T);   // grid = 256
}

// round 12
// speedup vs baseline: 1.1570x; 1.1570x over previous
#include <cuda_runtime.h>
#include <cstdint>

// MoE gating, exact fp32, K-packed f32x2 GEMM, explicit fragment pipeline.
// x:[16384,1024] f32, gate_w:[64,1024] f32.
// out (f32): top_scores [T,2] | top_idx [T,2] | total_loss [1].

#define H      1024
#define NE     64
#define TM     128
#define NT     256
#define KC     32
#define NSTEP  16                  // 512 k per half / KC
#define RS     36                  // smem row stride (floats)
#define XLo    0
#define XHi    (128 * RS)          // 4608
#define WLo    (256 * RS)          // 9216
#define WHi    (WLo + 64 * RS)     // 11520
#define STG    (WHi + 64 * RS)     // 13824 floats / stage
#define DSMEM  (2 * STG * 4)       // 110592 B
#define SPS    65
#define NBLK   128

__device__ float    g_pexp[NBLK * NE];
__device__ float    g_pz2[NBLK];
__device__ unsigned g_cnt = 0;

typedef unsigned long long ull;

__device__ __forceinline__ void fma2(ull& d, ull a, ull b) {
    asm("fma.rn.f32x2 %0, %1, %2, %0;" : "+l"(d) : "l"(a), "l"(b));
}
__device__ __forceinline__ uint32_t su32(const void* p) {
    uint32_t a;
    asm("{ .reg .u64 t; cvta.to.shared.u64 t, %1; cvt.u32.u64 %0, t; }"
        : "=r"(a) : "l"(p));
    return a;
}
__device__ __forceinline__ void cpa16(uint32_t dst, const float* src) {
    asm volatile("cp.async.cg.shared.global [%0], [%1], 16;" :: "r"(dst), "l"(src));
}

__global__ void __launch_bounds__(NT, 1) moe_gate(const float* __restrict__ x,
                                                  const float* __restrict__ w,
                                                  float* __restrict__ out,
                                                  int T) {
    extern __shared__ __align__(16) float dsm[];
    __shared__ float    s_red[8];
    __shared__ unsigned s_last;

    const int tid  = threadIdx.x;
    const int wid  = tid >> 5;
    const int lid  = tid & 31;
    const int tBlk = blockIdx.x * TM;
    const uint32_t sb = su32(dsm);

    // compute map (identical to R9)
    const int khalf = wid >> 2;            // 0: k<512, 1: k>=512
    const int wq    = wid & 3;
    const int tx    = lid & 7;             // experts {tx+8j}
    const int ty    = lid >> 3;
    const int g     = wq * 4 + ty;         // tokens {g+16i}

    ull acc[8][8];
#pragma unroll
    for (int i = 0; i < 8; i++)
#pragma unroll
        for (int j = 0; j < 8; j++) acc[i][j] = 0ull;

    const int sq = tid & 7;

#define STAGE(s_, slot_) do {                                                    \
    int _k0 = (s_) * KC;                                                         \
    uint32_t _sbase = sb + (slot_) * (STG * 4);                                  \
    _Pragma("unroll")                                                            \
    for (int r = 0; r < 4; r++) {                                                \
        int t_ = (r * 256 + tid) >> 3;                                           \
        const float* srcL = x + (size_t)(tBlk + t_) * H + _k0 + sq * 4;          \
        cpa16(_sbase + (XLo + t_ * RS + sq * 4) * 4, srcL);                      \
        cpa16(_sbase + (XHi + t_ * RS + sq * 4) * 4, srcL + 512);                \
    }                                                                            \
    _Pragma("unroll")                                                            \
    for (int r = 0; r < 2; r++) {                                                \
        int e_ = (r * 256 + tid) >> 3;                                           \
        const float* srcW = w + (size_t)e_ * H + _k0 + sq * 4;                   \
        cpa16(_sbase + (WLo + e_ * RS + sq * 4) * 4, srcW);                      \
        cpa16(_sbase + (WHi + e_ * RS + sq * 4) * 4, srcW + 512);                \
    }                                                                            \
} while (0)

    STAGE(0, 0);
    asm volatile("cp.async.commit_group;" ::: "memory");

#pragma unroll 1
    for (int s = 0; s < NSTEP; s++) {
        asm volatile("cp.async.wait_group 0;" ::: "memory");
        __syncthreads();
        if (s + 1 < NSTEP) STAGE(s + 1, (s + 1) & 1);
        asm volatile("cp.async.commit_group;" ::: "memory");

        const float* xs = dsm + (s & 1) * STG + (khalf ? XHi : XLo) + g * RS;
        const float* ws = dsm + (s & 1) * STG + (khalf ? WHi : WLo) + tx * RS;

        // explicit double-buffered fragment pipeline over 16 k-pairs
        ull a0[8], b0[8], a1[8], b1[8];
#pragma unroll
        for (int i = 0; i < 8; i++) a0[i] = *(const ull*)(xs + i * 16 * RS);
#pragma unroll
        for (int j = 0; j < 8; j++) b0[j] = *(const ull*)(ws + j * 8 * RS);
#pragma unroll
        for (int kh = 0; kh < 16; kh += 2) {
            // prefetch kh+1 into set 1
#pragma unroll
            for (int i = 0; i < 8; i++)
                a1[i] = *(const ull*)(xs + i * 16 * RS + 2 * (kh + 1));
#pragma unroll
            for (int j = 0; j < 8; j++)
                b1[j] = *(const ull*)(ws + j * 8 * RS + 2 * (kh + 1));
            // compute kh with set 0
#pragma unroll
            for (int i = 0; i < 8; i++)
#pragma unroll
                for (int j = 0; j < 8; j++)
                    fma2(acc[i][j], a0[i], b0[j]);
            // prefetch kh+2 into set 0
            if (kh + 2 < 16) {
#pragma unroll
                for (int i = 0; i < 8; i++)
                    a0[i] = *(const ull*)(xs + i * 16 * RS + 2 * (kh + 2));
#pragma unroll
                for (int j = 0; j < 8; j++)
                    b0[j] = *(const ull*)(ws + j * 8 * RS + 2 * (kh + 2));
            }
            // compute kh+1 with set 1
#pragma unroll
            for (int i = 0; i < 8; i++)
#pragma unroll
                for (int j = 0; j < 8; j++)
                    fma2(acc[i][j], a1[i], b1[j]);
        }
    }
    __syncthreads();

    // ---- merge k-halves: logits -> sP[128][SPS] ----
    float* sP   = dsm;
    float* sInv = dsm + 128 * SPS;
    if (khalf == 0) {
#pragma unroll
        for (int i = 0; i < 8; i++)
#pragma unroll
            for (int j = 0; j < 8; j++) {
                float2 f = *(float2*)&acc[i][j];
                sP[(g + 16 * i) * SPS + tx + 8 * j] = f.x + f.y;
            }
    }
    __syncthreads();
    if (khalf == 1) {
#pragma unroll
        for (int i = 0; i < 8; i++)
#pragma unroll
            for (int j = 0; j < 8; j++) {
                float2 f = *(float2*)&acc[i][j];
                sP[(g + 16 * i) * SPS + tx + 8 * j] += f.x + f.y;
            }
    }
    __syncthreads();

    // ---- per-token softmax / top-2 ----
    float zsq = 0.0f;
    if (tid < TM) {
        float* row = sP + tid * SPS;
        float b1v = -1e30f, b2v = -1e30f;
        int   i1 = 0, i2 = 0;
#pragma unroll 8
        for (int e = 0; e < NE; e++) {
            float l = row[e];
            if (l > b1v)      { b2v = b1v; i2 = i1; b1v = l; i1 = e; }
            else if (l > b2v) { b2v = l;  i2 = e; }
        }
        float m = b1v, sum = 0.0f;
#pragma unroll 8
        for (int e = 0; e < NE; e++) {
            float ex = __expf(row[e] - m);
            sum += ex;
            row[e] = ex;
        }
        float inv = 1.0f / sum;
        sInv[tid] = inv;
        float z = m + __logf(sum);
        zsq = z * z;
        float p1 = __expf(b1v - m) * inv;
        float p2 = __expf(b2v - m) * inv;
        float dd = __expf(p2 - p1);
        int gt = tBlk + tid;
        out[2 * gt]             = 1.0f / (1.0f + dd);
        out[2 * gt + 1]         = dd / (1.0f + dd);
        out[2 * T + 2 * gt]     = (float)i1;
        out[2 * T + 2 * gt + 1] = (float)i2;
    }

    // ---- loss partials ----
#pragma unroll
    for (int off = 16; off > 0; off >>= 1)
        zsq += __shfl_down_sync(0xffffffffu, zsq, off);
    if (lid == 0) s_red[wid] = zsq;
    __syncthreads();
    if (tid == 0) {
        float s = 0.0f;
#pragma unroll
        for (int i = 0; i < 8; i++) s += s_red[i];
        g_pz2[blockIdx.x] = s;
    }
    if (tid < NE) {
        float s = 0.0f;
#pragma unroll 4
        for (int t = 0; t < TM; t++) s += sP[t * SPS + tid] * sInv[t];
        g_pexp[blockIdx.x * NE + tid] = s;
    }

    // ---- fused finalize ----
    __threadfence();
    __syncthreads();
    if (tid == 0)
        s_last = (atomicAdd(&g_cnt, 1u) == (unsigned)(gridDim.x - 1)) ? 1u : 0u;
    __syncthreads();
    if (s_last) {
        __threadfence();
        int e = tid & 63, part = tid >> 6;
        float s = 0.0f;
#pragma unroll 4
        for (int b = part; b < NBLK; b += 4) s += g_pexp[b * NE + e];
        float z2 = (tid < NBLK) ? g_pz2[tid] : 0.0f;
        __syncthreads();
        float* redA = dsm;
        float* redZ = dsm + 256;
        redA[part * 64 + e] = s;
        redZ[tid] = z2;
        __syncthreads();
        if (tid < 64) {
            float load = (redA[tid] + redA[64 + tid] + redA[128 + tid] + redA[192 + tid]) / (float)T;
            float dv = load - 1.0f / 64.0f;
            float lb = dv * dv;
            float zz = redZ[tid] + redZ[tid + 64] + redZ[tid + 128] + redZ[tid + 192];
#pragma unroll
            for (int off = 16; off > 0; off >>= 1) {
                lb += __shfl_down_sync(0xffffffffu, lb, off);
                zz += __shfl_down_sync(0xffffffffu, zz, off);
            }
            if (lid == 0) { s_red[wid] = lb; s_red[4 + wid] = zz; }
        }
        __syncthreads();
        if (tid == 0) {
            out[4 * T] = 0.01f * 64.0f * (s_red[0] + s_red[1])
                       + 1e-4f * ((s_red[4] + s_red[5]) / (float)T);
            g_cnt = 0;
        }
    }
}

extern "C" void kernel_launch(void* const* d_in, const int* in_sizes, int n_in,
                              void* d_out, int out_size) {
    const float* x = (const float*)d_in[0];
    const float* w = (const float*)d_in[1];
    float* out = (float*)d_out;
    int T = in_sizes[0] / H;   // 16384
    cudaFuncSetAttribute(moe_gate, cudaFuncAttributeMaxDynamicSharedMemorySize, DSMEM);
    moe_gate<<<T / TM, NT, DSMEM>>>(x, w, out, T);   // grid = 128
}

// round 13
// speedup vs baseline: 1.1952x; 1.0331x over previous
#include <cuda_runtime.h>
#include <cstdint>

// MoE gating, exact fp32, K-packed f32x2 GEMM, LDS.128 pair frags, 3-stage ring.
// x:[16384,1024] f32, gate_w:[64,1024] f32.
// out (f32): top_scores [T,2] | top_idx [T,2] | total_loss [1].

#define H      1024
#define NE     64
#define TM     128
#define NT     256
#define KC     32
#define NSTEP  16                  // 512 k per half / KC
#define RS     36                  // smem row stride (floats)
#define XLo    0
#define XHi    (128 * RS)          // 4608
#define WLo    (256 * RS)          // 9216
#define WHi    (WLo + 64 * RS)     // 11520
#define STG    (WHi + 64 * RS)     // 13824 floats / stage
#define DSMEM  (3 * STG * 4)       // 165888 B
#define SPS    65
#define NBLK   128

__device__ float    g_pexp[NBLK * NE];
__device__ float    g_pz2[NBLK];
__device__ unsigned g_cnt = 0;

typedef unsigned long long ull;

__device__ __forceinline__ void fma2(ull& d, ull a, ull b) {
    asm("fma.rn.f32x2 %0, %1, %2, %0;" : "+l"(d) : "l"(a), "l"(b));
}
__device__ __forceinline__ uint32_t su32(const void* p) {
    uint32_t a;
    asm("{ .reg .u64 t; cvta.to.shared.u64 t, %1; cvt.u32.u64 %0, t; }"
        : "=r"(a) : "l"(p));
    return a;
}
__device__ __forceinline__ void cpa16(uint32_t dst, const float* src) {
    asm volatile("cp.async.cg.shared.global [%0], [%1], 16;" :: "r"(dst), "l"(src));
}

__global__ void __launch_bounds__(NT, 1) moe_gate(const float* __restrict__ x,
                                                  const float* __restrict__ w,
                                                  float* __restrict__ out,
                                                  int T) {
    extern __shared__ __align__(16) float dsm[];
    __shared__ float    s_red[8];
    __shared__ unsigned s_last;

    const int tid  = threadIdx.x;
    const int wid  = tid >> 5;
    const int lid  = tid & 31;
    const int tBlk = blockIdx.x * TM;
    const uint32_t sb = su32(dsm);

    // compute map (as R9/R12)
    const int khalf = wid >> 2;            // 0: k<512, 1: k>=512
    const int wq    = wid & 3;
    const int tx    = lid & 7;             // experts {tx+8j}
    const int ty    = lid >> 3;
    const int g     = wq * 4 + ty;         // tokens {g+16i}

    ull acc[8][8];
#pragma unroll
    for (int i = 0; i < 8; i++)
#pragma unroll
        for (int j = 0; j < 8; j++) acc[i][j] = 0ull;

    const int sq = tid & 7;

#define STAGE(s_, slot_) do {                                                    \
    int _k0 = (s_) * KC;                                                         \
    uint32_t _sbase = sb + (slot_) * (STG * 4);                                  \
    _Pragma("unroll")                                                            \
    for (int r = 0; r < 4; r++) {                                                \
        int t_ = (r * 256 + tid) >> 3;                                           \
        const float* srcL = x + (size_t)(tBlk + t_) * H + _k0 + sq * 4;          \
        cpa16(_sbase + (XLo + t_ * RS + sq * 4) * 4, srcL);                      \
        cpa16(_sbase + (XHi + t_ * RS + sq * 4) * 4, srcL + 512);                \
    }                                                                            \
    _Pragma("unroll")                                                            \
    for (int r = 0; r < 2; r++) {                                                \
        int e_ = (r * 256 + tid) >> 3;                                           \
        const float* srcW = w + (size_t)e_ * H + _k0 + sq * 4;                   \
        cpa16(_sbase + (WLo + e_ * RS + sq * 4) * 4, srcW);                      \
        cpa16(_sbase + (WHi + e_ * RS + sq * 4) * 4, srcW + 512);                \
    }                                                                            \
} while (0)

    // prologue: fill stages 0 and 1
    STAGE(0, 0);
    asm volatile("cp.async.commit_group;" ::: "memory");
    STAGE(1, 1);
    asm volatile("cp.async.commit_group;" ::: "memory");

#pragma unroll 1
    for (int s = 0; s < NSTEP; s++) {
        asm volatile("cp.async.wait_group 1;" ::: "memory");   // stage s done
        __syncthreads();
        if (s + 2 < NSTEP) {
            int slot = (s + 2) % 3;
            STAGE(s + 2, slot);
        }
        asm volatile("cp.async.commit_group;" ::: "memory");

        const float* xs = dsm + (s % 3) * STG + (khalf ? XHi : XLo) + g * RS;
        const float* ws = dsm + (s % 3) * STG + (khalf ? WHi : WLo) + tx * RS;

        // 8 pair-blocks; each LDS.128 fetches k-pairs (2kh, 2kh+1)
#pragma unroll
        for (int blk = 0; blk < 8; blk++) {
            ulonglong2 a[8], b[8];
#pragma unroll
            for (int i = 0; i < 8; i++)
                a[i] = *(const ulonglong2*)(xs + i * 16 * RS + 4 * blk);
#pragma unroll
            for (int j = 0; j < 8; j++)
                b[j] = *(const ulonglong2*)(ws + j * 8 * RS + 4 * blk);
#pragma unroll
            for (int i = 0; i < 8; i++)
#pragma unroll
                for (int j = 0; j < 8; j++)
                    fma2(acc[i][j], a[i].x, b[j].x);
#pragma unroll
            for (int i = 0; i < 8; i++)
#pragma unroll
                for (int j = 0; j < 8; j++)
                    fma2(acc[i][j], a[i].y, b[j].y);
        }
    }
    __syncthreads();

    // ---- merge k-halves: logits -> sP[128][SPS] ----
    float* sP    = dsm;
    float* sInv  = dsm + 128 * SPS;        // 128 floats
    float* sLoad = sInv + 128;             // [4][64]
    if (khalf == 0) {
#pragma unroll
        for (int i = 0; i < 8; i++)
#pragma unroll
            for (int j = 0; j < 8; j++) {
                float2 f = *(float2*)&acc[i][j];
                sP[(g + 16 * i) * SPS + tx + 8 * j] = f.x + f.y;
            }
    }
    __syncthreads();
    if (khalf == 1) {
#pragma unroll
        for (int i = 0; i < 8; i++)
#pragma unroll
            for (int j = 0; j < 8; j++) {
                float2 f = *(float2*)&acc[i][j];
                sP[(g + 16 * i) * SPS + tx + 8 * j] += f.x + f.y;
            }
    }
    __syncthreads();

    // ---- per-token softmax / top-2 ----
    float zsq = 0.0f;
    if (tid < TM) {
        float* row = sP + tid * SPS;
        float b1v = -1e30f, b2v = -1e30f;
        int   i1 = 0, i2 = 0;
#pragma unroll 8
        for (int e = 0; e < NE; e++) {
            float l = row[e];
            if (l > b1v)      { b2v = b1v; i2 = i1; b1v = l; i1 = e; }
            else if (l > b2v) { b2v = l;  i2 = e; }
        }
        float m = b1v, sum = 0.0f;
#pragma unroll 8
        for (int e = 0; e < NE; e++) {
            float ex = __expf(row[e] - m);
            sum += ex;
            row[e] = ex;
        }
        float inv = 1.0f / sum;
        sInv[tid] = inv;
        float z = m + __logf(sum);
        zsq = z * z;
        float p1 = __expf(b1v - m) * inv;
        float p2 = __expf(b2v - m) * inv;
        float dd = __expf(p2 - p1);
        int gt = tBlk + tid;
        out[2 * gt]             = 1.0f / (1.0f + dd);
        out[2 * gt + 1]         = dd / (1.0f + dd);
        out[2 * T + 2 * gt]     = (float)i1;
        out[2 * T + 2 * gt + 1] = (float)i2;
    }

    // ---- z-loss partial ----
#pragma unroll
    for (int off = 16; off > 0; off >>= 1)
        zsq += __shfl_down_sync(0xffffffffu, zsq, off);
    if (lid == 0) s_red[wid] = zsq;
    __syncthreads();
    if (tid == 0) {
        float s = 0.0f;
#pragma unroll
        for (int i = 0; i < 8; i++) s += s_red[i];
        g_pz2[blockIdx.x] = s;
    }

    // ---- expert-load partial, parallel over all 256 threads ----
    {
        int e = tid & 63, q = tid >> 6;    // q: token quarter (32 tokens)
        float s = 0.0f;
#pragma unroll 8
        for (int t = 0; t < 32; t++) {
            int tok = q * 32 + t;
            s += sP[tok * SPS + e] * sInv[tok];
        }
        sLoad[q * 64 + e] = s;
    }
    __syncthreads();
    if (tid < NE)
        g_pexp[blockIdx.x * NE + tid] = sLoad[tid] + sLoad[64 + tid]
                                      + sLoad[128 + tid] + sLoad[192 + tid];

    // ---- fused finalize ----
    __threadfence();
    __syncthreads();
    if (tid == 0)
        s_last = (atomicAdd(&g_cnt, 1u) == (unsigned)(gridDim.x - 1)) ? 1u : 0u;
    __syncthreads();
    if (s_last) {
        __threadfence();
        int e = tid & 63, part = tid >> 6;
        float s = 0.0f;
#pragma unroll 4
        for (int b = part; b < NBLK; b += 4) s += g_pexp[b * NE + e];
        float z2 = (tid < NBLK) ? g_pz2[tid] : 0.0f;
        __syncthreads();
        float* redA = dsm;
        float* redZ = dsm + 256;
        redA[part * 64 + e] = s;
        redZ[tid] = z2;
        __syncthreads();
        if (tid < 64) {
            float load = (redA[tid] + redA[64 + tid] + redA[128 + tid] + redA[192 + tid]) / (float)T;
            float dv = load - 1.0f / 64.0f;
            float lb = dv * dv;
            float zz = redZ[tid] + redZ[tid + 64] + redZ[tid + 128] + redZ[tid + 192];
#pragma unroll
            for (int off = 16; off > 0; off >>= 1) {
                lb += __shfl_down_sync(0xffffffffu, lb, off);
                zz += __shfl_down_sync(0xffffffffu, zz, off);
            }
            if (lid == 0) { s_red[wid] = lb; s_red[4 + wid] = zz; }
        }
        __syncthreads();
        if (tid == 0) {
            out[4 * T] = 0.01f * 64.0f * (s_red[0] + s_red[1])
                       + 1e-4f * ((s_red[4] + s_red[5]) / (float)T);
            g_cnt = 0;
        }
    }
}

extern "C" void kernel_launch(void* const* d_in, const int* in_sizes, int n_in,
                              void* d_out, int out_size) {
    const float* x = (const float*)d_in[0];
    const float* w = (const float*)d_in[1];
    float* out = (float*)d_out;
    int T = in_sizes[0] / H;   // 16384
    cudaFuncSetAttribute(moe_gate, cudaFuncAttributeMaxDynamicSharedMemorySize, DSMEM);
    moe_gate<<<T / TM, NT, DSMEM>>>(x, w, out, T);   // grid = 128
}